// round 3
// baseline (speedup 1.0000x reference)
#include <cuda_runtime.h>
#include <math.h>

// Problem constants (fixed by setup_inputs)
#define BB 32
#define EE 256
#define HH 512
#define VV 32000
#define TT 128

#define NBLK 125          // 125 * 256 = 32000 threads = V
#define NTHR 256
#define XS 260            // x smem row stride (floats), 16B aligned, conflict-spread
#define HSA 516           // h smem row stride (floats) for phase A
#define SMEM_FLOATS (BB*XS + BB*HSA)   // 24832 floats = 99328 B (phase A view)
#define SMEM_BYTES (SMEM_FLOATS*4)

// ---------------- device globals (no allocation allowed) ----------------
__device__ float g_h[2][BB*HH];                 // double-buffered hidden state
__device__ unsigned long long g_amax[2][BB];    // packed (value,idx) argmax per batch
__device__ unsigned g_barcnt;
__device__ unsigned g_barflag;

// ---------------- helpers ----------------
__device__ __forceinline__ void ffma2(unsigned long long& d,
                                      unsigned long long a,
                                      unsigned long long b) {
    // packed 2x fp32 FMA: d = a*b + d (elementwise on the two lanes)
    asm("fma.rn.f32x2 %0, %1, %2, %0;" : "+l"(d) : "l"(a), "l"(b));
}
__device__ __forceinline__ unsigned long long dl(double d) {
    return __double_as_longlong(d);
}
__device__ __forceinline__ float red2(unsigned long long a) {
    return __uint_as_float((unsigned)a) + __uint_as_float((unsigned)(a >> 32));
}
__device__ __forceinline__ unsigned long long packcand(float val, int v) {
    unsigned u = __float_as_uint(val);
    u = (u & 0x80000000u) ? ~u : (u | 0x80000000u);   // order-preserving map
    // lower 32 = 0xFFFFFFFF - v  -> ties resolve to the SMALLEST index (jnp.argmax)
    return ((unsigned long long)u << 32) | (unsigned long long)(0xFFFFFFFFu - (unsigned)v);
}

// sense-counting grid barrier (all NBLK blocks resident: 125 <= 148 SMs, 1 blk/SM)
__device__ __forceinline__ void grid_sync(unsigned& gen) {
    gen++;
    __threadfence();
    __syncthreads();
    if (threadIdx.x == 0) {
        unsigned prev = atomicAdd(&g_barcnt, 1);
        if (prev == NBLK - 1) {
            atomicExch(&g_barcnt, 0);
            __threadfence();
            *(volatile unsigned*)&g_barflag = gen;
        } else {
            while (*(volatile unsigned*)&g_barflag < gen) { }
        }
    }
    __syncthreads();
}

// ---------------- init (runs each replay; makes launch deterministic) ----------------
__global__ void init_kernel(const float* __restrict__ ctx) {
    int i = blockIdx.x * blockDim.x + threadIdx.x;
    if (i < BB * HH) g_h[0][i] = ctx[i];
    if (i == 0) { g_barcnt = 0; g_barflag = 0; }
}

// ---------------- main persistent decoder ----------------
__global__ void __launch_bounds__(NTHR, 1)
decoder_kernel(const float* __restrict__ embed,
               const float* __restrict__ w_ih,
               const float* __restrict__ w_hh,
               const float* __restrict__ b_ih,
               const float* __restrict__ b_hh,
               const float* __restrict__ fc_w,
               const float* __restrict__ fc_b,
               float* __restrict__ out,
               float* __restrict__ pred) {
    extern __shared__ float smem[];
    const int tid  = threadIdx.x;
    const int gtid = blockIdx.x * NTHR + tid;
    unsigned gen = 0;
    __shared__ int tok_sh[BB];

    const bool doA = (blockIdx.x < (BB * HH) / NTHR);   // first 64 blocks run GRU

    for (int t = 0; t < TT; ++t) {
        const float* hsrc = g_h[t & 1];
        float*       hdst = g_h[(t + 1) & 1];

        // ===================== Phase A: token decode + GRU cell =====================
        if (doA) {
            if (tid < BB) {
                int tk;
                if (t == 0) {
                    tk = 1;  // START_IDX
                } else {
                    unsigned long long p =
                        *(volatile unsigned long long*)&g_amax[(t - 1) & 1][tid];
                    tk = (int)(0xFFFFFFFFu - (unsigned)(p & 0xFFFFFFFFull));
                }
                tok_sh[tid] = tk;
                if (blockIdx.x == 0) {
                    if (t > 0 && pred) pred[(size_t)tid * TT + (t - 1)] = (float)tk;
                    // reset this step's argmax buffer (last read at phase A of t-1)
                    *(volatile unsigned long long*)&g_amax[t & 1][tid] = 0ull;
                }
            }
            __syncthreads();

            float* xs  = smem;              // [BB][XS]
            float* hsA = smem + BB * XS;    // [BB][HSA]

            // stage x = embed[tok]  (32x256)
            for (int i = tid; i < BB * (EE / 4); i += NTHR) {
                int b = i / (EE / 4), k = (i % (EE / 4)) * 4;
                float4 v = *(const float4*)(embed + (size_t)tok_sh[b] * EE + k);
                *(float4*)(xs + b * XS + k) = v;
            }
            // stage h_old (L2-bypass: written by other SMs last step)
            for (int i = tid; i < BB * (HH / 4); i += NTHR) {
                int b = i / (HH / 4), k = (i % (HH / 4)) * 4;
                float4 v = __ldcg((const float4*)(hsrc + (size_t)b * HH + k));
                *(float4*)(hsA + b * HSA + k) = v;
            }
            __syncthreads();

            const int pair = gtid;       // < 16384 for doA blocks
            const int b = pair & 31;     // lane = batch -> warp-uniform weight rows
            const int i = pair >> 5;

            unsigned long long a_ir = 0, a_iz = 0, a_in = 0;
            unsigned long long a_hr = 0, a_hz = 0, a_hn = 0;
            {
                const double2* wr = (const double2*)(w_ih + (size_t)i * EE);
                const double2* wz = wr + (size_t)HH * EE / 4;
                const double2* wn = wr + (size_t)2 * HH * EE / 4;
                const double2* xv = (const double2*)(xs + b * XS);
                #pragma unroll 4
                for (int k = 0; k < EE / 4; k++) {
                    double2 x2 = xv[k];
                    double2 r2 = __ldg(wr + k);
                    double2 z2 = __ldg(wz + k);
                    double2 n2 = __ldg(wn + k);
                    ffma2(a_ir, dl(r2.x), dl(x2.x)); ffma2(a_ir, dl(r2.y), dl(x2.y));
                    ffma2(a_iz, dl(z2.x), dl(x2.x)); ffma2(a_iz, dl(z2.y), dl(x2.y));
                    ffma2(a_in, dl(n2.x), dl(x2.x)); ffma2(a_in, dl(n2.y), dl(x2.y));
                }
            }
            {
                const double2* wr = (const double2*)(w_hh + (size_t)i * HH);
                const double2* wz = wr + (size_t)HH * HH / 4;
                const double2* wn = wr + (size_t)2 * HH * HH / 4;
                const double2* hv = (const double2*)(hsA + b * HSA);
                #pragma unroll 4
                for (int k = 0; k < HH / 4; k++) {
                    double2 h2 = hv[k];
                    double2 r2 = __ldg(wr + k);
                    double2 z2 = __ldg(wz + k);
                    double2 n2 = __ldg(wn + k);
                    ffma2(a_hr, dl(r2.x), dl(h2.x)); ffma2(a_hr, dl(r2.y), dl(h2.y));
                    ffma2(a_hz, dl(z2.x), dl(h2.x)); ffma2(a_hz, dl(z2.y), dl(h2.y));
                    ffma2(a_hn, dl(n2.x), dl(h2.x)); ffma2(a_hn, dl(n2.y), dl(h2.y));
                }
            }
            float ir  = red2(a_ir) + __ldg(b_ih + i);
            float iz  = red2(a_iz) + __ldg(b_ih + HH + i);
            float inn = red2(a_in) + __ldg(b_ih + 2 * HH + i);
            float hr  = red2(a_hr) + __ldg(b_hh + i);
            float hz  = red2(a_hz) + __ldg(b_hh + HH + i);
            float hn  = red2(a_hn) + __ldg(b_hh + 2 * HH + i);
            float r = 1.0f / (1.0f + expf(-(ir + hr)));
            float z = 1.0f / (1.0f + expf(-(iz + hz)));
            float n = tanhf(fmaf(r, hn, inn));
            float hold = hsA[b * HSA + i];
            hdst[(size_t)b * HH + i] = n + z * (hold - n);
        }

        grid_sync(gen);

        // ===================== Phase B: logits GEMM + argmax =====================
        {
            float* hb = smem;                                            // [BB][HH]
            unsigned long long* wbuf = (unsigned long long*)(smem + BB * HH);
            const float* hsrcB = g_h[(t + 1) & 1];
            for (int i = tid; i < BB * (HH / 4); i += NTHR) {
                float4 v = __ldcg((const float4*)(hsrcB + (size_t)i * 4));
                *(float4*)(hb + i * 4) = v;
            }
            __syncthreads();

            const int v = gtid;   // exactly one logit column per thread (grid == V)
            const double2* wrow = (const double2*)(fc_w + (size_t)v * HH);
            const double2* hpBase = (const double2*)hb;

            unsigned long long acc[BB];
            #pragma unroll
            for (int b = 0; b < BB; b++) acc[b] = 0ull;

            #pragma unroll 2
            for (int k = 0; k < HH / 4; k++) {
                double2 wd = __ldcg(wrow + k);
                unsigned long long w01 = dl(wd.x);
                unsigned long long w23 = dl(wd.y);
                const double2* hp = hpBase + k;
                #pragma unroll
                for (int b = 0; b < BB; b++) {
                    double2 h2 = hp[b * (HH / 4)];       // broadcast LDS.128
                    ffma2(acc[b], w01, dl(h2.x));
                    ffma2(acc[b], w23, dl(h2.y));
                }
            }

            const float bias = __ldg(fc_b + v);
            const int wid = tid >> 5, lane = tid & 31;

            #pragma unroll
            for (int b = 0; b < BB; b++) {
                float f = red2(acc[b]) + bias;
                out[((size_t)b * TT + t) * VV + v] = f;    // coalesced across warp
                unsigned long long p = packcand(f, v);
                #pragma unroll
                for (int off = 16; off; off >>= 1) {
                    unsigned long long q = __shfl_xor_sync(0xffffffffu, p, off);
                    if (q > p) p = q;
                }
                if (lane == 0) wbuf[wid * BB + b] = p;
            }
            __syncthreads();
            if (tid < BB) {
                unsigned long long best = wbuf[tid];
                #pragma unroll
                for (int w = 1; w < NTHR / 32; w++) {
                    unsigned long long q = wbuf[w * BB + tid];
                    if (q > best) best = q;
                }
                atomicMax(&g_amax[t & 1][tid], best);
            }
        }

        grid_sync(gen);
    }

    // final step's predictions
    if (blockIdx.x == 0 && tid < BB && pred) {
        unsigned long long p =
            *(volatile unsigned long long*)&g_amax[(TT - 1) & 1][tid];
        pred[(size_t)tid * TT + (TT - 1)] =
            (float)(0xFFFFFFFFu - (unsigned)(p & 0xFFFFFFFFull));
    }
}

// ---------------- host launch ----------------
extern "C" void kernel_launch(void* const* d_in, const int* in_sizes, int n_in,
                              void* d_out, int out_size) {
    (void)in_sizes; (void)n_in;
    const float* ctx   = (const float*)d_in[0];
    const float* embed = (const float*)d_in[1];
    const float* w_ih  = (const float*)d_in[2];
    const float* w_hh  = (const float*)d_in[3];
    const float* b_ih  = (const float*)d_in[4];
    const float* b_hh  = (const float*)d_in[5];
    const float* fc_w  = (const float*)d_in[6];
    const float* fc_b  = (const float*)d_in[7];
    // d_in[8] = max_target_seq_len (device scalar) -- fixed to 128 for this problem

    float* out = (float*)d_out;
    const long long logits_elems = (long long)BB * TT * VV;
    float* pred = ((long long)out_size >= logits_elems + (long long)BB * TT)
                      ? out + logits_elems : nullptr;

    cudaFuncSetAttribute(decoder_kernel,
                         cudaFuncAttributeMaxDynamicSharedMemorySize, SMEM_BYTES);

    init_kernel<<<(BB * HH + 255) / 256, 256>>>(ctx);
    decoder_kernel<<<NBLK, NTHR, SMEM_BYTES>>>(embed, w_ih, w_hh, b_ih, b_hh,
                                               fc_w, fc_b, out, pred);
}